// round 2
// baseline (speedup 1.0000x reference)
#include <cuda_runtime.h>
#include <cstdint>
#include <cstddef>

// DPQNetwork: r[b,c,k] = sum_d X[b,c,d]*Yc[c,k,d]; BN over (B,K) per channel;
// outputs: codes=argmax_k (as f32), mse=max_k of normalized r, centroids copy.
// BN is a per-channel monotone-increasing affine map (gamma=1 in this problem),
// so argmax/max commute with it: take max of RAW r, apply the affine afterward.
// => r (8192x64x256 = 537 MB) is never written to HBM.

#define NB 8192
#define NC 64
#define NK 256
#define ND 64
#define GRIDX 128          // NB / 64 rows per block
#define PAD 68             // padded smem row stride (floats)

// Deterministic scratch (no device-side allocation allowed).
__device__ float g_psum[NC * GRIDX];
__device__ float g_psumsq[NC * GRIDX];
__device__ float g_affA[NC];
__device__ float g_affB[NC];

__global__ __launch_bounds__(256, 2) void dpq_main(
    const float* __restrict__ X,    // (B, C, D)
    const float* __restrict__ Yc,   // (C, K, D)
    float* __restrict__ out)        // [0,B*C): codes  [B*C,2B*C): raw max
{
    extern __shared__ float sm[];
    float* Xs   = sm;                       // 64  * PAD
    float* Ys   = Xs + 64 * PAD;            // 256 * PAD
    float* smax = Ys + 256 * PAD;           // 8 warps * 64 rows
    int*   sidx = (int*)(smax + 512);       // 8 * 64
    float* wsum = (float*)(sidx + 512);     // 8
    float* wsq  = wsum + 8;                 // 8

    const int c    = blockIdx.y;
    const int b0   = blockIdx.x * 64;
    const int tid  = threadIdx.x;
    const int lane = tid & 31;
    const int warp = tid >> 5;
    const int bsub = lane & 7;              // 8 b-subgroups of 8 rows
    const int kq   = lane >> 3;             // 4 k-quarters per warp
    const int kbase = (warp * 4 + kq) * 8;  // this thread's 8 k columns

    // ---- stage tiles: X rows [b0,b0+64) of channel c, full Y[c] (256x64) ----
#pragma unroll
    for (int s = 0; s < 4; s++) {
        int idx = s * 256 + tid;
        int row = idx >> 4, q = idx & 15;
        float4 v = ((const float4*)(X + ((size_t)(b0 + row) * NC + c) * ND))[q];
        *(float4*)(Xs + row * PAD + q * 4) = v;
    }
    const float* Yg = Yc + (size_t)c * NK * ND;
#pragma unroll
    for (int s = 0; s < 16; s++) {
        int idx = s * 256 + tid;
        int row = idx >> 4, q = idx & 15;
        float4 v = ((const float4*)(Yg + row * ND))[q];
        *(float4*)(Ys + row * PAD + q * 4) = v;
    }
    __syncthreads();

    // ---- 8x8 register tile, d vectorized by 4 ----
    float acc[8][8];
#pragma unroll
    for (int i = 0; i < 8; i++)
#pragma unroll
        for (int j = 0; j < 8; j++) acc[i][j] = 0.f;

    const float* xbase = Xs + bsub * 8 * PAD;
    const float* ybase = Ys + kbase * PAD;

#pragma unroll 2
    for (int s = 0; s < 16; s++) {
        float4 xv[8];
#pragma unroll
        for (int i = 0; i < 8; i++)
            xv[i] = *(const float4*)(xbase + i * PAD + s * 4);
#pragma unroll
        for (int j = 0; j < 8; j++) {
            float4 yv = *(const float4*)(ybase + j * PAD + s * 4);
#pragma unroll
            for (int i = 0; i < 8; i++) {
                acc[i][j] = fmaf(xv[i].x, yv.x, acc[i][j]);
                acc[i][j] = fmaf(xv[i].y, yv.y, acc[i][j]);
                acc[i][j] = fmaf(xv[i].z, yv.z, acc[i][j]);
                acc[i][j] = fmaf(xv[i].w, yv.w, acc[i][j]);
            }
        }
    }

    // ---- thread-local max/argmax per row + sum / sumsq for BN stats ----
    float s1 = 0.f, s2 = 0.f;
    float tmax[8]; int tidx[8];
#pragma unroll
    for (int i = 0; i < 8; i++) {
        tmax[i] = acc[i][0]; tidx[i] = kbase;
#pragma unroll
        for (int j = 0; j < 8; j++) {
            float v = acc[i][j];
            s1 += v;
            s2 = fmaf(v, v, s2);
            if (v > tmax[i]) { tmax[i] = v; tidx[i] = kbase + j; }
        }
    }

    // reduce max across the 4 k-quarters in this warp (xor 8,16 keeps bsub)
#pragma unroll
    for (int i = 0; i < 8; i++) {
#pragma unroll
        for (int off = 8; off <= 16; off <<= 1) {
            float v2 = __shfl_xor_sync(0xffffffffu, tmax[i], off);
            int   i2 = __shfl_xor_sync(0xffffffffu, tidx[i], off);
            if (v2 > tmax[i] || (v2 == tmax[i] && i2 < tidx[i])) {
                tmax[i] = v2; tidx[i] = i2;
            }
        }
    }
    if (kq == 0) {
#pragma unroll
        for (int i = 0; i < 8; i++) {
            smax[warp * 64 + bsub * 8 + i] = tmax[i];
            sidx[warp * 64 + bsub * 8 + i] = tidx[i];
        }
    }

    // warp sum for BN stats
#pragma unroll
    for (int off = 16; off > 0; off >>= 1) {
        s1 += __shfl_xor_sync(0xffffffffu, s1, off);
        s2 += __shfl_xor_sync(0xffffffffu, s2, off);
    }
    if (lane == 0) { wsum[warp] = s1; wsq[warp] = s2; }
    __syncthreads();

    // cross-warp max per row; write codes + raw max
    if (tid < 64) {
        const int row = tid;
        float m = smax[row]; int ki = sidx[row];
#pragma unroll
        for (int w = 1; w < 8; w++) {
            float v = smax[w * 64 + row]; int i2 = sidx[w * 64 + row];
            if (v > m || (v == m && i2 < ki)) { m = v; ki = i2; }
        }
        const size_t o = (size_t)(b0 + row) * NC + c;
        out[o] = (float)ki;                        // codes
        out[(size_t)NB * NC + o] = m;              // raw max (normalized later)
    }
    if (tid == 0) {
        float a = 0.f, b = 0.f;
#pragma unroll
        for (int w = 0; w < 8; w++) { a += wsum[w]; b += wsq[w]; }
        g_psum[c * GRIDX + blockIdx.x]   = a;      // deterministic: one writer
        g_psumsq[c * GRIDX + blockIdx.x] = b;
    }
}

__global__ void dpq_stats(const float* __restrict__ gamma,
                          const float* __restrict__ beta)
{
    const int c = threadIdx.x;          // 64 threads
    float s = 0.f, q = 0.f;
    for (int i = 0; i < GRIDX; i++) {
        s += g_psum[c * GRIDX + i];
        q += g_psumsq[c * GRIDX + i];
    }
    const float inv = 1.0f / ((float)NB * (float)NK);
    const float mean = s * inv;
    const float var  = q * inv - mean * mean;   // biased, matches reference
    const float a = gamma[c] * rsqrtf(var + 1e-5f);
    g_affA[c] = a;
    g_affB[c] = fmaf(-mean, a, beta[c]);
}

__global__ void dpq_final(float* __restrict__ out)
{
    const int idx = blockIdx.x * blockDim.x + threadIdx.x;
    if (idx < NB * NC) {
        const int c = idx & (NC - 1);
        float* p = out + (size_t)NB * NC + idx;
        *p = fmaf(*p, g_affA[c], g_affB[c]);
    }
}

extern "C" void kernel_launch(void* const* d_in, const int* in_sizes, int n_in,
                              void* d_out, int out_size)
{
    const float* X     = (const float*)d_in[0];  // inputs (B,C,D)
    const float* Yc    = (const float*)d_in[1];  // centroids_k (C,K,D)
    const float* gamma = (const float*)d_in[2];
    const float* beta  = (const float*)d_in[3];
    float* out = (float*)d_out;

    const size_t smem = (size_t)(64 * PAD + 256 * PAD + 512 + 512 + 16) * sizeof(float);
    cudaFuncSetAttribute(dpq_main, cudaFuncAttributeMaxDynamicSharedMemorySize, (int)smem);

    dim3 grid(GRIDX, NC);
    dpq_main<<<grid, 256, smem>>>(X, Yc, out);
    dpq_stats<<<1, NC>>>(gamma, beta);
    dpq_final<<<(NB * NC + 255) / 256, 256>>>(out);

    // Third output: centroids_k passed through unchanged.
    if (out_size >= 2 * NB * NC + NC * NK * ND) {
        cudaMemcpyAsync(out + 2 * (size_t)NB * NC, Yc,
                        (size_t)NC * NK * ND * sizeof(float),
                        cudaMemcpyDeviceToDevice, 0);
    }
}

// round 3
// speedup vs baseline: 2.3841x; 2.3841x over previous
#include <cuda_runtime.h>
#include <cstdint>
#include <cstddef>

// DPQNetwork: r[b,c,k] = sum_d X[b,c,d]*Yc[c,k,d]; BN over (B,K) per channel;
// outputs: codes=argmax_k (f32), mse=max_k normalized, centroids pass-through.
// BN is a monotone-increasing per-channel affine (gamma=1) => argmax/max on RAW
// r, affine applied afterward; r (537 MB) never touches HBM.
//
// R2 changes vs R1 (L1=93.7% bound):
//  - X rows per thread = bsub + i*8 (lanes read consecutive rows, 272B stride
//    => disjoint bank spans, conflict-free; old mapping was 8-way conflicted).
//  - fma.rn.f32x2 packed FMA; Y staged in smem as k-pair-interleaved u64 so a
//    single LDS.64 returns a packed (Y[2k][d],Y[2k+1][d]) operand.

#define NB 8192
#define NC 64
#define NK 256
#define ND 64
#define GRIDX 128            // NB / 64 rows per block
#define XPAD 68              // X smem row stride (floats)
#define YSTRIDE 130          // Y smem row stride (u64 per d-row: 128 pairs + pad)

__device__ float g_psum[NC * GRIDX];
__device__ float g_psumsq[NC * GRIDX];
__device__ float g_affA[NC];
__device__ float g_affB[NC];

__device__ __forceinline__ unsigned long long f32x2_dup(float x) {
    unsigned long long r;
    asm("mov.b64 %0, {%1, %1};" : "=l"(r) : "f"(x));
    return r;
}
__device__ __forceinline__ unsigned long long f32x2_pack(float lo, float hi) {
    unsigned long long r;
    asm("mov.b64 %0, {%1, %2};" : "=l"(r) : "f"(lo), "f"(hi));
    return r;
}
__device__ __forceinline__ void f32x2_fma(unsigned long long& acc,
                                          unsigned long long a,
                                          unsigned long long b) {
    asm("fma.rn.f32x2 %0, %1, %2, %0;" : "+l"(acc) : "l"(a), "l"(b));
}
__device__ __forceinline__ void f32x2_unpack(unsigned long long v,
                                             float& lo, float& hi) {
    asm("mov.b64 {%0, %1}, %2;" : "=f"(lo), "=f"(hi) : "l"(v));
}

__global__ __launch_bounds__(256, 2) void dpq_main(
    const float* __restrict__ X,    // (B, C, D)
    const float* __restrict__ Yc,   // (C, K, D)
    float* __restrict__ out)        // [0,B*C): codes  [B*C,2B*C): raw max
{
    extern __shared__ char smraw[];
    unsigned long long* Ys2 = (unsigned long long*)smraw;        // 64 * YSTRIDE u64
    float* Xs   = (float*)(Ys2 + 64 * YSTRIDE);                  // 64 * XPAD
    float* smax = Xs + 64 * XPAD;                                // 8 warps * 64
    int*   sidx = (int*)(smax + 512);                            // 8 * 64
    float* wsum = (float*)(sidx + 512);                          // 8
    float* wsq  = wsum + 8;                                      // 8

    const int c    = blockIdx.y;
    const int b0   = blockIdx.x * 64;
    const int tid  = threadIdx.x;
    const int lane = tid & 31;
    const int warp = tid >> 5;
    const int bsub = lane & 7;               // lane's base b-row (rows bsub+8i)
    const int kq   = lane >> 3;              // 4 k-quarters per warp
    const int kp0  = (warp * 4 + kq) * 4;    // first k-PAIR index (4 pairs=8 k)

    // ---- stage X rows [b0,b0+64) of channel c ----
#pragma unroll
    for (int s = 0; s < 4; s++) {
        int idx = s * 256 + tid;
        int row = idx >> 4, q = idx & 15;
        float4 v = ((const float4*)(X + ((size_t)(b0 + row) * NC + c) * ND))[q];
        *(float4*)(Xs + row * XPAD + q * 4) = v;
    }
    // ---- stage Y[c] transposed into k-pair-packed u64: Ys2[d][kp] ----
    const float* Yg = Yc + (size_t)c * NK * ND;
#pragma unroll
    for (int t = 0; t < 8; t++) {
        int idx = t * 256 + tid;             // 0..2047
        int kp = idx & 127, dc = idx >> 7;   // dc: 16 chunks of 4 d
        float4 a = *(const float4*)(Yg + (2 * kp)     * ND + dc * 4);
        float4 b = *(const float4*)(Yg + (2 * kp + 1) * ND + dc * 4);
        Ys2[(dc * 4 + 0) * YSTRIDE + kp] = f32x2_pack(a.x, b.x);
        Ys2[(dc * 4 + 1) * YSTRIDE + kp] = f32x2_pack(a.y, b.y);
        Ys2[(dc * 4 + 2) * YSTRIDE + kp] = f32x2_pack(a.z, b.z);
        Ys2[(dc * 4 + 3) * YSTRIDE + kp] = f32x2_pack(a.w, b.w);
    }
    __syncthreads();

    // ---- 8 b-rows x 8 k-cols per thread; acc as 4 packed f32x2 per row ----
    unsigned long long acc[8][4];
#pragma unroll
    for (int i = 0; i < 8; i++)
#pragma unroll
        for (int j = 0; j < 4; j++) acc[i][j] = 0ull;

    const float* xrow = Xs + bsub * XPAD;

#pragma unroll 2
    for (int d = 0; d < ND; d += 2) {
        float2 xv[8];
#pragma unroll
        for (int i = 0; i < 8; i++)
            xv[i] = *(const float2*)(xrow + i * 8 * XPAD + d);
        unsigned long long yv0[4], yv1[4];
#pragma unroll
        for (int j = 0; j < 4; j++) {
            yv0[j] = Ys2[(d)     * YSTRIDE + kp0 + j];
            yv1[j] = Ys2[(d + 1) * YSTRIDE + kp0 + j];
        }
#pragma unroll
        for (int i = 0; i < 8; i++) {
            unsigned long long x0 = f32x2_dup(xv[i].x);
            unsigned long long x1 = f32x2_dup(xv[i].y);
#pragma unroll
            for (int j = 0; j < 4; j++) {
                f32x2_fma(acc[i][j], x0, yv0[j]);
                f32x2_fma(acc[i][j], x1, yv1[j]);
            }
        }
    }

    // ---- per-row max/argmax + BN partial sums ----
    float s1 = 0.f, s2 = 0.f;
    float tmax[8]; int tidx[8];
#pragma unroll
    for (int i = 0; i < 8; i++) {
        tmax[i] = -3.4e38f; tidx[i] = 0;
#pragma unroll
        for (int j = 0; j < 4; j++) {
            float lo, hi;
            f32x2_unpack(acc[i][j], lo, hi);
            s1 += lo + hi;
            s2 = fmaf(lo, lo, s2);
            s2 = fmaf(hi, hi, s2);
            int klo = (kp0 + j) * 2;
            if (lo > tmax[i]) { tmax[i] = lo; tidx[i] = klo; }
            if (hi > tmax[i]) { tmax[i] = hi; tidx[i] = klo + 1; }
        }
    }

    // reduce max across 4 k-quarters in warp (xor 8,16 keeps bsub fixed)
#pragma unroll
    for (int i = 0; i < 8; i++) {
#pragma unroll
        for (int off = 8; off <= 16; off <<= 1) {
            float v2 = __shfl_xor_sync(0xffffffffu, tmax[i], off);
            int   i2 = __shfl_xor_sync(0xffffffffu, tidx[i], off);
            if (v2 > tmax[i] || (v2 == tmax[i] && i2 < tidx[i])) {
                tmax[i] = v2; tidx[i] = i2;
            }
        }
    }
    if (kq == 0) {
#pragma unroll
        for (int i = 0; i < 8; i++) {
            smax[warp * 64 + bsub + i * 8] = tmax[i];   // row = bsub + 8i
            sidx[warp * 64 + bsub + i * 8] = tidx[i];
        }
    }

    // warp sum for BN stats
#pragma unroll
    for (int off = 16; off > 0; off >>= 1) {
        s1 += __shfl_xor_sync(0xffffffffu, s1, off);
        s2 += __shfl_xor_sync(0xffffffffu, s2, off);
    }
    if (lane == 0) { wsum[warp] = s1; wsq[warp] = s2; }
    __syncthreads();

    // cross-warp max per row; write codes + raw max
    if (tid < 64) {
        const int row = tid;
        float m = smax[row]; int ki = sidx[row];
#pragma unroll
        for (int w = 1; w < 8; w++) {
            float v = smax[w * 64 + row]; int i2 = sidx[w * 64 + row];
            if (v > m || (v == m && i2 < ki)) { m = v; ki = i2; }
        }
        const size_t o = (size_t)(b0 + row) * NC + c;
        out[o] = (float)ki;
        out[(size_t)NB * NC + o] = m;
    }
    if (tid == 0) {
        float a = 0.f, b = 0.f;
#pragma unroll
        for (int w = 0; w < 8; w++) { a += wsum[w]; b += wsq[w]; }
        g_psum[c * GRIDX + blockIdx.x]   = a;     // single writer, deterministic
        g_psumsq[c * GRIDX + blockIdx.x] = b;
    }
}

__global__ void dpq_stats(const float* __restrict__ gamma,
                          const float* __restrict__ beta)
{
    const int c = threadIdx.x;          // 64 threads
    float s = 0.f, q = 0.f;
    for (int i = 0; i < GRIDX; i++) {
        s += g_psum[c * GRIDX + i];
        q += g_psumsq[c * GRIDX + i];
    }
    const float inv = 1.0f / ((float)NB * (float)NK);
    const float mean = s * inv;
    const float var  = q * inv - mean * mean;   // biased, matches reference
    const float a = gamma[c] * rsqrtf(var + 1e-5f);
    g_affA[c] = a;
    g_affB[c] = fmaf(-mean, a, beta[c]);
}

__global__ void dpq_final(float* __restrict__ out)
{
    const int idx = blockIdx.x * blockDim.x + threadIdx.x;
    if (idx < NB * NC) {
        const int c = idx & (NC - 1);
        float* p = out + (size_t)NB * NC + idx;
        *p = fmaf(*p, g_affA[c], g_affB[c]);
    }
}

extern "C" void kernel_launch(void* const* d_in, const int* in_sizes, int n_in,
                              void* d_out, int out_size)
{
    const float* X     = (const float*)d_in[0];  // inputs (B,C,D)
    const float* Yc    = (const float*)d_in[1];  // centroids_k (C,K,D)
    const float* gamma = (const float*)d_in[2];
    const float* beta  = (const float*)d_in[3];
    float* out = (float*)d_out;

    const size_t smem = (size_t)64 * YSTRIDE * 8     // Ys2 u64
                      + (size_t)64 * XPAD * 4        // Xs
                      + 512 * 4 + 512 * 4 + 16 * 4;  // reductions
    cudaFuncSetAttribute(dpq_main, cudaFuncAttributeMaxDynamicSharedMemorySize,
                         (int)smem);

    dim3 grid(GRIDX, NC);
    dpq_main<<<grid, 256, smem>>>(X, Yc, out);
    dpq_stats<<<1, NC>>>(gamma, beta);
    dpq_final<<<(NB * NC + 255) / 256, 256>>>(out);

    if (out_size >= 2 * NB * NC + NC * NK * ND) {
        cudaMemcpyAsync(out + 2 * (size_t)NB * NC, Yc,
                        (size_t)NC * NK * ND * sizeof(float),
                        cudaMemcpyDeviceToDevice, 0);
    }
}